// round 9
// baseline (speedup 1.0000x reference)
#include <cuda_runtime.h>
#include <cstdint>

#define TSTEPS 512
#define BSZ    256
#define DIN    128
#define HID    256
#define NPROTO 128
#define DHTOT  384
#define NB     8            // batches per cluster
#define CSZ    4            // CTAs per cluster
#define NTHR   512
#define NCTA   128

__device__ float4 g_Wpack[NPROTO][HID];          // [p][h] = {wf, wi, wg, wo}
__device__ float4 g_protoPack[DHTOT/4][NPROTO];  // [q][p] = proto[p][4q..4q+3]
__device__ float  g_pn2[NPROTO];
__device__ unsigned long long g_PP[DIN][NPROTO/2];
__device__ float  g_DOTX[(size_t)TSTEPS*BSZ*NPROTO]; // dot(x,proto_x) - 0.5*||x||^2

typedef unsigned long long u64;

// ---------------- qlstm smem layout (bytes) ----------------
// PROT: [16 q][128 p] float4      32768  @ 0
// PG  : [8 pc][8 b][2 fi][64 h]   65536  @ 32768
// KD  : [128 p][10 u64]           10240  @ 98304
// DOT : [2 buf][4 r][4 pr][128 p] 32768  @ 108544
// CN2 : [2 buf][4 r][4 pr] u64      256  @ 141312
// CMB : [4 pr][8 hp][4 dc][2] u64  2048  @ 141568  (hv; {b_even,b_odd})
#define PROT_OFF 0
#define PG_OFF   32768
#define KD_OFF   98304
#define DOT_OFF  108544
#define CN2_OFF  141312
#define CMB_OFF  141568
#define SMEM_TOTAL 143616

__device__ __forceinline__ u64 pk2(float lo, float hi){
    u64 r; asm("mov.b64 %0, {%1,%2};" : "=l"(r) : "f"(lo), "f"(hi)); return r;
}
__device__ __forceinline__ void upk2(u64 v, float& lo, float& hi){
    asm("mov.b64 {%0,%1}, %2;" : "=f"(lo), "=f"(hi) : "l"(v));
}
__device__ __forceinline__ u64 ffma2(u64 a, u64 b, u64 c){
    u64 d; asm("fma.rn.f32x2 %0, %1, %2, %3;" : "=l"(d) : "l"(a), "l"(b), "l"(c)); return d;
}
__device__ __forceinline__ u64 add2(u64 a, u64 b){
    u64 d; asm("add.rn.f32x2 %0, %1, %2;" : "=l"(d) : "l"(a), "l"(b)); return d;
}
__device__ __forceinline__ float sigmf(float x){
    return __fdividef(1.f, 1.f + __expf(-x));
}
__device__ __forceinline__ float tanhf_(float x){
    return 1.f - __fdividef(2.f, __expf(2.f*x) + 1.f);
}
__device__ __forceinline__ uint32_t smem_u32(const void* p){
    uint32_t a;
    asm("{ .reg .u64 t; cvta.to.shared.u64 t, %1; cvt.u32.u64 %0, t; }" : "=r"(a) : "l"(p));
    return a;
}
__device__ __forceinline__ uint32_t ctarank(){
    uint32_t r; asm("mov.u32 %0, %%cluster_ctarank;" : "=r"(r)); return r;
}
__device__ __forceinline__ uint32_t mapa_u32(uint32_t local, uint32_t rank){
    uint32_t r; asm("mapa.shared::cluster.u32 %0, %1, %2;" : "=r"(r) : "r"(local), "r"(rank));
    return r;
}
__device__ __forceinline__ void st_cl64(uint32_t addr, u64 v){
    asm volatile("st.shared::cluster.b64 [%0], %1;" :: "r"(addr), "l"(v) : "memory");
}
__device__ __forceinline__ void cl_arrive(){
    asm volatile("barrier.cluster.arrive.aligned;" ::: "memory");
}
__device__ __forceinline__ void cl_wait(){
    asm volatile("barrier.cluster.wait.aligned;"   ::: "memory");
}
__device__ __forceinline__ u64 shfl_xor64(u64 v, int off){
    uint32_t lo = (uint32_t)v, hi = (uint32_t)(v >> 32);
    lo = __shfl_xor_sync(0xffffffffu, lo, off);
    hi = __shfl_xor_sync(0xffffffffu, hi, off);
    return ((u64)hi << 32) | lo;
}

// ============ pack ============
__global__ void pack_kernel(const float* __restrict__ proto,
                            const float* __restrict__ Wf, const float* __restrict__ Wi,
                            const float* __restrict__ Wg, const float* __restrict__ Wo){
    int idx = blockIdx.x * blockDim.x + threadIdx.x;
    if (idx < HID*NPROTO){
        int h = idx >> 7, pp = idx & (NPROTO-1);
        g_Wpack[pp][h] = make_float4(Wf[idx], Wi[idx], Wg[idx], Wo[idx]);
    }
    if (idx < (DHTOT/4)*NPROTO){
        int q = idx >> 7, pp = idx & (NPROTO-1);
        const float* pr = proto + pp*DHTOT + 4*q;
        g_protoPack[q][pp] = make_float4(pr[0], pr[1], pr[2], pr[3]);
    }
    if (idx < DIN*(NPROTO/2)){
        int d = idx >> 6, pp = idx & 63;
        g_PP[d][pp] = pk2(proto[(2*pp)*DHTOT + d], proto[(2*pp+1)*DHTOT + d]);
    }
    if (idx < NPROTO){
        float s = 0.f;
        for (int d = 0; d < DHTOT; ++d){ float v = proto[idx*DHTOT + d]; s = fmaf(v, v, s); }
        g_pn2[idx] = s;
    }
}

// ============ DOTX precompute ============
extern __shared__ char psm[];
__global__ __launch_bounds__(512, 1)
void dotx_kernel(const float* __restrict__ x){
    u64* PPs = reinterpret_cast<u64*>(psm);        // [128 d][64 pp]
    const int tid = threadIdx.x;
    const int lane = tid & 31, wrp = tid >> 5;
    #pragma unroll
    for (int i = 0; i < 16; ++i)
        PPs[tid + i*512] = ((const u64*)g_PP)[tid + i*512];
    __syncthreads();

    const int pg = lane & 7;
    const int rp = (wrp << 2) | (lane >> 3);
    const size_t r0 = (size_t)blockIdx.x*128 + rp*2;
    const float4* xr0 = reinterpret_cast<const float4*>(x + r0*DIN);
    const float4* xr1 = reinterpret_cast<const float4*>(x + (r0+1)*DIN);

    u64 accA[8], accB[8];
    #pragma unroll
    for (int i = 0; i < 8; ++i){ accA[i] = 0ull; accB[i] = 0ull; }
    float n0 = 0.f, n1 = 0.f;

    #pragma unroll 4
    for (int dq = 0; dq < 32; ++dq){
        float4 fa = __ldcg(&xr0[dq]);
        float4 fb = __ldcg(&xr1[dq]);
        const float a[4] = {fa.x, fa.y, fa.z, fa.w};
        const float b[4] = {fb.x, fb.y, fb.z, fb.w};
        #pragma unroll
        for (int l = 0; l < 4; ++l){
            int d = dq*4 + l;
            u64 va = pk2(a[l], a[l]);
            u64 vb = pk2(b[l], b[l]);
            n0 = fmaf(a[l], a[l], n0);
            n1 = fmaf(b[l], b[l], n1);
            const u64* row = PPs + d*64 + pg;
            #pragma unroll
            for (int i = 0; i < 8; ++i){
                u64 pv = row[i*8];
                accA[i] = ffma2(va, pv, accA[i]);
                accB[i] = ffma2(vb, pv, accB[i]);
            }
        }
    }
    u64 nA2 = pk2(-0.5f*n0, -0.5f*n0);
    u64 nB2 = pk2(-0.5f*n1, -0.5f*n1);
    u64* DX = reinterpret_cast<u64*>(g_DOTX);
    #pragma unroll
    for (int i = 0; i < 8; ++i){
        int pp = i*8 + pg;
        DX[r0*64 + pp]     = add2(accA[i], nA2);
        DX[(r0+1)*64 + pp] = add2(accB[i], nB2);
    }
}

// ============ recurrent kernel ============
extern __shared__ char sm[];

__global__ void __cluster_dims__(CSZ,1,1) __launch_bounds__(NTHR, 1)
qlstm_kernel(const float* __restrict__ bf, const float* __restrict__ bi,
             const float* __restrict__ bg, const float* __restrict__ bo,
             float* __restrict__ out){
    const int tid  = threadIdx.x;
    const int lane = tid & 31;
    const int wrp  = tid >> 5;
    const uint32_t rank = ctarank();
    const int bbase = (blockIdx.x >> 2) * NB;
    const uint32_t base = smem_u32(sm);

    float4* PROT = reinterpret_cast<float4*>(sm + PROT_OFF);
    u64*    PGp  = reinterpret_cast<u64*>(sm + PG_OFF);
    u64*    KD   = reinterpret_cast<u64*>(sm + KD_OFF);
    const ulonglong2* KDv2 = reinterpret_cast<const ulonglong2*>(sm + KD_OFF);
    u64*    DOT  = reinterpret_cast<u64*>(sm + DOT_OFF);
    u64*    CN2  = reinterpret_cast<u64*>(sm + CN2_OFF);
    u64*    CMBu = reinterpret_cast<u64*>(sm + CMB_OFF);   // [pr][hp][dc][2]
    float*  CMBF = reinterpret_cast<float*>(sm + CMB_OFF);
    const ulonglong2* CMB2 = reinterpret_cast<const ulonglong2*>(sm + CMB_OFF);

    // roles
    const int pDl = (wrp << 3) + (lane & 7);    // dist p (0..127)
    const int dcl = lane >> 3;                  // dist h-chunk (0..3) in lane bits
    const int prF = ((dcl & 1) << 1) | (dcl >> 1);  // pair this thread finalizes
    const int pK  = tid & 127;                  // K p
    const int prK = tid >> 7;                   // K pair
    const int hL  = tid & 63;                   // gate/reduce h_local
    const int pcG = tid >> 6;                   // gate p-chunk (0..7)
    const int bR  = tid >> 6;                   // reduce batch (0..7)
    const int hglob = (int)rank*64 + hL;

    // ---------- preamble ----------
    #pragma unroll
    for (int i = 0; i < 4; ++i){
        int idx = tid + i*NTHR;
        int q = idx >> 7, p = idx & 127;
        PROT[q*128 + p] = g_protoPack[32 + (int)rank*16 + q][p];
    }
    u64 wFI[16], wGO[16];
    #pragma unroll
    for (int j = 0; j < 16; ++j){
        float4 w = g_Wpack[pcG*16 + j][hglob];
        wFI[j] = pk2(w.x, w.y);
        wGO[j] = pk2(w.z, w.w);
    }
    if (tid < 256) CMBu[tid] = 0ull;            // zero hv

    const u64 bFI = pk2(bf[hglob], bi[hglob]);
    const u64 bGO = pk2(bg[hglob], bo[hglob]);
    const float pn2v = g_pn2[pK];

    // DSMEM addresses
    uint32_t dotA[CSZ], cnA[CSZ];
    {
        uint32_t dOff = base + DOT_OFF + (uint32_t)((((rank*4) + prF)*128 + pDl)*8);
        uint32_t cOff = base + CN2_OFF + (uint32_t)((rank*4 + wrp)*8);  // cn2 role (tid<128)
        #pragma unroll
        for (uint32_t r = 0; r < CSZ; ++r){
            dotA[r] = mapa_u32(dOff, r);
            cnA[r]  = mapa_u32(cOff, r);
        }
    }

    const float* __restrict__ dxbase = g_DOTX + (size_t)(bbase + 2*prK)*NPROTO + pK;

    float cx = 0.f, hv = 0.f;

    __syncthreads();
    cl_arrive(); cl_wait();

    for (int t = 0; t < TSTEPS; ++t){
        const uint32_t bufDot = (uint32_t)(t & 1) * 16384u;
        const uint32_t bufCn  = (uint32_t)(t & 1) * 128u;
        const int      bufU   = (t & 1) * 2048;
        const int      bufC   = (t & 1) * 16;

        // prefetch DOTX (consumed in K after the barrier)
        const float* dxp = dxbase + (size_t)t*BSZ*NPROTO;
        float dxa = __ldcg(dxp);
        float dxb = __ldcg(dxp + NPROTO);

        __syncthreads();                // S1: hv(t-1) visible locally

        // ---- dist: thread=(pDl, dcl), 16 h slice, all 4 pairs ----
        {
            u64 a0 = 0ull, a1 = 0ull, a2 = 0ull, a3 = 0ull;
            const float4* pp = PROT + (dcl*4)*128 + pDl;
            #pragma unroll
            for (int i = 0; i < 4; ++i){
                float4 pv = pp[i*128];
                u64 v0 = pk2(pv.x, pv.x), v1 = pk2(pv.y, pv.y);
                u64 v2 = pk2(pv.z, pv.z), v3 = pk2(pv.w, pv.w);
                #pragma unroll
                for (int pr = 0; pr < 4; ++pr){
                    ulonglong2 cA = CMB2[pr*32 + (2*i  )*4 + dcl];
                    ulonglong2 cB = CMB2[pr*32 + (2*i+1)*4 + dcl];
                    u64 acc = (pr==0)?a0:(pr==1)?a1:(pr==2)?a2:a3;
                    acc = ffma2(cA.x, v0, acc);
                    acc = ffma2(cA.y, v1, acc);
                    acc = ffma2(cB.x, v2, acc);
                    acc = ffma2(cB.y, v3, acc);
                    if (pr==0) a0=acc; else if (pr==1) a1=acc; else if (pr==2) a2=acc; else a3=acc;
                }
            }
            // butterfly over dc (lane bits 3,4); thread ends with pair prF
            u64 s0 = (dcl & 1) ? a0 : a2;
            u64 s1 = (dcl & 1) ? a1 : a3;
            u64 r0 = shfl_xor64(s0, 8);
            u64 r1 = shfl_xor64(s1, 8);
            u64 A  = add2((dcl & 1) ? a2 : a0, r0);
            u64 B  = add2((dcl & 1) ? a3 : a1, r1);
            u64 s2 = (dcl & 2) ? A : B;
            u64 r2 = shfl_xor64(s2, 16);
            u64 fin = add2((dcl & 2) ? B : A, r2);
            #pragma unroll
            for (int r = 0; r < CSZ; ++r) st_cl64(dotA[r] + bufDot, fin);
        }

        // ---- cn2 partial (warps 0-3: pr = wrp) ----
        if (tid < 128){
            const u64* cb = CMBu + wrp*64;
            u64 c0 = cb[lane], c1 = cb[lane + 32];
            u64 a = ffma2(c0, c0, ffma2(c1, c1, 0ull));
            #pragma unroll
            for (int off = 16; off; off >>= 1)
                a = add2(a, shfl_xor64(a, off));
            if (lane == 0){
                #pragma unroll
                for (int r = 0; r < CSZ; ++r) st_cl64(cnA[r] + bufCn, a);
            }
        }

        cl_arrive();
        cl_wait();                      // all ranks' partials visible

        // ---- k: reduce ranks + DOTX + exp ----
        {
            const u64* db = DOT + bufU;
            u64 ds =        db[(0*4 + prK)*128 + pK];
            ds = add2(ds,   db[(1*4 + prK)*128 + pK]);
            ds = add2(ds,   db[(2*4 + prK)*128 + pK]);
            ds = add2(ds,   db[(3*4 + prK)*128 + pK]);
            const u64* cn = CN2 + bufC;
            u64 cs = add2(add2(cn[0*4 + prK], cn[1*4 + prK]),
                          add2(cn[2*4 + prK], cn[3*4 + prK]));
            float d0, d1, c0, c1;
            upk2(ds, d0, d1); upk2(cs, c0, c1);
            float k0 = __expf(2.f*(d0 + dxa) - pn2v - c0);
            float k1 = __expf(2.f*(d1 + dxb) - pn2v - c1);
            ulonglong2 kk; kk.x = pk2(k0, k0); kk.y = pk2(k1, k1);
            *reinterpret_cast<ulonglong2*>(KD + pK*10 + 2*prK) = kk;
        }
        __syncthreads();                // S3: KD ready

        // ---- gate GEMM: thread=(hL, pcG), 16 p, 8 batches ----
        {
            u64 F0=0,F1=0,F2=0,F3=0,F4=0,F5=0,F6=0,F7=0;
            u64 G0=0,G1=0,G2=0,G3=0,G4=0,G5=0,G6=0,G7=0;
            const ulonglong2* kp = KDv2 + (pcG*16)*5;
            #pragma unroll 4
            for (int j = 0; j < 16; ++j){
                ulonglong2 kA = kp[j*5 + 0];
                ulonglong2 kB = kp[j*5 + 1];
                ulonglong2 kC = kp[j*5 + 2];
                ulonglong2 kE = kp[j*5 + 3];
                F0 = ffma2(wFI[j], kA.x, F0);  G0 = ffma2(wGO[j], kA.x, G0);
                F1 = ffma2(wFI[j], kA.y, F1);  G1 = ffma2(wGO[j], kA.y, G1);
                F2 = ffma2(wFI[j], kB.x, F2);  G2 = ffma2(wGO[j], kB.x, G2);
                F3 = ffma2(wFI[j], kB.y, F3);  G3 = ffma2(wGO[j], kB.y, G3);
                F4 = ffma2(wFI[j], kC.x, F4);  G4 = ffma2(wGO[j], kC.x, G4);
                F5 = ffma2(wFI[j], kC.y, F5);  G5 = ffma2(wGO[j], kC.y, G5);
                F6 = ffma2(wFI[j], kE.x, F6);  G6 = ffma2(wGO[j], kE.x, G6);
                F7 = ffma2(wFI[j], kE.y, F7);  G7 = ffma2(wGO[j], kE.y, G7);
            }
            u64* pg = PGp + (pcG*8)*2*64 + hL;
            pg[(0*2+0)*64] = F0; pg[(0*2+1)*64] = G0;
            pg[(1*2+0)*64] = F1; pg[(1*2+1)*64] = G1;
            pg[(2*2+0)*64] = F2; pg[(2*2+1)*64] = G2;
            pg[(3*2+0)*64] = F3; pg[(3*2+1)*64] = G3;
            pg[(4*2+0)*64] = F4; pg[(4*2+1)*64] = G4;
            pg[(5*2+0)*64] = F5; pg[(5*2+1)*64] = G5;
            pg[(6*2+0)*64] = F6; pg[(6*2+1)*64] = G6;
            pg[(7*2+0)*64] = F7; pg[(7*2+1)*64] = G7;
        }
        __syncthreads();                // S4: PG ready

        // ---- reduce + activations: thread=(hL, bR) ----
        {
            u64 Fa = bFI, Ga = bGO;
            #pragma unroll
            for (int c = 0; c < 8; ++c){
                Fa = add2(Fa, PGp[((c*8 + bR)*2 + 0)*64 + hL]);
                Ga = add2(Ga, PGp[((c*8 + bR)*2 + 1)*64 + hL]);
            }
            float fp, ip, gp, op;
            upk2(Fa, fp, ip); upk2(Ga, gp, op);
            float fv = sigmf(fp), iv = sigmf(ip), gv = tanhf_(gp), ov = sigmf(op);
            cx = fv*cx + iv*gv;
            hv = ov * tanhf_(cx);
            // hv -> CMB [pr][hp][dc][hl01], float half = batch parity
            int u64idx = (bR >> 1)*64 + ((hL & 15) >> 1)*8 + (hL >> 4)*2 + (hL & 1);
            CMBF[u64idx*2 + (bR & 1)] = hv;
            out[((size_t)t*BSZ + bbase + bR)*HID + hglob] = hv;
        }
        // loop-top S1 orders hv before next dist; DOT/CN2 double-buffer +
        // single cluster barrier per step handles cross-CTA WAR.
    }

    // ---- finals ----
    {
        const size_t TBH = (size_t)TSTEPS * BSZ * HID;
        const size_t BH  = (size_t)BSZ * HID;
        out[TBH + (size_t)(bbase + bR)*HID + hglob] = hv;
        out[TBH + BH + (size_t)(bbase + bR)*HID + hglob] = cx;
    }
}

extern "C" void kernel_launch(void* const* d_in, const int* in_sizes, int n_in,
                              void* d_out, int out_size){
    (void)in_sizes; (void)n_in; (void)out_size;
    const float* inputs = (const float*)d_in[0];
    const float* proto  = (const float*)d_in[1];
    const float* Wf     = (const float*)d_in[2];
    const float* bf     = (const float*)d_in[3];
    const float* Wi     = (const float*)d_in[4];
    const float* bi     = (const float*)d_in[5];
    const float* Wg     = (const float*)d_in[6];
    const float* bg     = (const float*)d_in[7];
    const float* Wo     = (const float*)d_in[8];
    const float* bo     = (const float*)d_in[9];
    float* out = (float*)d_out;

    cudaFuncSetAttribute(qlstm_kernel,
                         cudaFuncAttributeMaxDynamicSharedMemorySize, SMEM_TOTAL);
    cudaFuncSetAttribute(dotx_kernel,
                         cudaFuncAttributeMaxDynamicSharedMemorySize, 65536);

    pack_kernel<<<(HID*NPROTO + 511)/512, 512>>>(proto, Wf, Wi, Wg, Wo);
    dotx_kernel<<<(TSTEPS*BSZ)/128, 512, 65536>>>(inputs);
    qlstm_kernel<<<NCTA, NTHR, SMEM_TOTAL>>>(bf, bi, bg, bo, out);
}

// round 10
// speedup vs baseline: 1.4389x; 1.4389x over previous
#include <cuda_runtime.h>
#include <cstdint>

#define TSTEPS 512
#define BSZ    256
#define DIN    128
#define HID    256
#define NPROTO 128
#define DHTOT  384
#define NB     8            // batches per cluster
#define CSZ    4            // CTAs per cluster
#define NTHR   512
#define NCTA   128

__device__ float4 g_Wpack[NPROTO][HID];          // [p][h] = {wf, wi, wg, wo}
__device__ float4 g_protoPack[DHTOT/4][NPROTO];  // [q][p] = proto[p][4q..4q+3]
__device__ float  g_pn2[NPROTO];
__device__ unsigned long long g_PP[DIN][NPROTO/2];
__device__ float  g_DOTX[(size_t)TSTEPS*BSZ*NPROTO]; // dot(x,proto_x) - 0.5*||x||^2

typedef unsigned long long u64;

// ---------------- qlstm smem layout (bytes) ----------------
// PROT: [16 q][128 p] float4      32768  @ 0
// PG  : [8 pc][8 b][2 fi][64 h]   65536  @ 32768
// KD  : [128 p][10 u64]           10240  @ 98304
// DOT : [2 buf][4 r][4 pr][128 p] 32768  @ 108544
// PD  : [4 dc][4 pr][128 p] u64   16384  @ 141312
// CN2 : [2 buf][4 r][4 pr] u64      256  @ 157696
// CMB : [4 pr][64 h] u64           2048  @ 157952
// MBAR: 1 u64                         8  @ 160000
#define PROT_OFF 0
#define PG_OFF   32768
#define KD_OFF   98304
#define DOT_OFF  108544
#define PD_OFF   141312
#define CN2_OFF  157696
#define CMB_OFF  157952
#define MBAR_OFF 160000
#define SMEM_TOTAL 160064

__device__ __forceinline__ u64 pk2(float lo, float hi){
    u64 r; asm("mov.b64 %0, {%1,%2};" : "=l"(r) : "f"(lo), "f"(hi)); return r;
}
__device__ __forceinline__ void upk2(u64 v, float& lo, float& hi){
    asm("mov.b64 {%0,%1}, %2;" : "=f"(lo), "=f"(hi) : "l"(v));
}
__device__ __forceinline__ u64 ffma2(u64 a, u64 b, u64 c){
    u64 d; asm("fma.rn.f32x2 %0, %1, %2, %3;" : "=l"(d) : "l"(a), "l"(b), "l"(c)); return d;
}
__device__ __forceinline__ u64 add2(u64 a, u64 b){
    u64 d; asm("add.rn.f32x2 %0, %1, %2;" : "=l"(d) : "l"(a), "l"(b)); return d;
}
__device__ __forceinline__ float sigmf(float x){
    return __fdividef(1.f, 1.f + __expf(-x));
}
__device__ __forceinline__ float tanhf_(float x){
    return 1.f - __fdividef(2.f, __expf(2.f*x) + 1.f);
}
__device__ __forceinline__ uint32_t smem_u32(const void* p){
    uint32_t a;
    asm("{ .reg .u64 t; cvta.to.shared.u64 t, %1; cvt.u32.u64 %0, t; }" : "=r"(a) : "l"(p));
    return a;
}
__device__ __forceinline__ uint32_t ctarank(){
    uint32_t r; asm("mov.u32 %0, %%cluster_ctarank;" : "=r"(r)); return r;
}
__device__ __forceinline__ uint32_t mapa_u32(uint32_t local, uint32_t rank){
    uint32_t r; asm("mapa.shared::cluster.u32 %0, %1, %2;" : "=r"(r) : "r"(local), "r"(rank));
    return r;
}
__device__ __forceinline__ void st_cl64(uint32_t addr, u64 v){
    asm volatile("st.shared::cluster.b64 [%0], %1;" :: "r"(addr), "l"(v) : "memory");
}
__device__ __forceinline__ void cl_arrive(){
    asm volatile("barrier.cluster.arrive.aligned;" ::: "memory");
}
__device__ __forceinline__ void cl_wait(){
    asm volatile("barrier.cluster.wait.aligned;"   ::: "memory");
}
__device__ __forceinline__ void mbar_init(uint32_t addr, uint32_t cnt){
    asm volatile("mbarrier.init.shared.b64 [%0], %1;" :: "r"(addr), "r"(cnt) : "memory");
}
__device__ __forceinline__ void mbar_arrive_cluster(uint32_t addr){
    asm volatile("mbarrier.arrive.release.cluster.shared::cluster.b64 _, [%0];"
                 :: "r"(addr) : "memory");
}
__device__ __forceinline__ void mbar_wait_par(uint32_t addr, uint32_t par){
    asm volatile(
        "{\n\t"
        ".reg .pred P;\n"
        "WL_%=:\n\t"
        "mbarrier.try_wait.parity.acquire.cluster.shared::cta.b64 P, [%0], %1, 0x989680;\n\t"
        "@!P bra WL_%=;\n\t"
        "}"
        :: "r"(addr), "r"(par) : "memory");
}
__device__ __forceinline__ u64 shfl_xor64(u64 v, int off){
    uint32_t lo = (uint32_t)v, hi = (uint32_t)(v >> 32);
    lo = __shfl_xor_sync(0xffffffffu, lo, off);
    hi = __shfl_xor_sync(0xffffffffu, hi, off);
    return ((u64)hi << 32) | lo;
}

// ============ pack ============
__global__ void pack_kernel(const float* __restrict__ proto,
                            const float* __restrict__ Wf, const float* __restrict__ Wi,
                            const float* __restrict__ Wg, const float* __restrict__ Wo){
    int idx = blockIdx.x * blockDim.x + threadIdx.x;
    if (idx < HID*NPROTO){
        int h = idx >> 7, pp = idx & (NPROTO-1);
        g_Wpack[pp][h] = make_float4(Wf[idx], Wi[idx], Wg[idx], Wo[idx]);
    }
    if (idx < (DHTOT/4)*NPROTO){
        int q = idx >> 7, pp = idx & (NPROTO-1);
        const float* pr = proto + pp*DHTOT + 4*q;
        g_protoPack[q][pp] = make_float4(pr[0], pr[1], pr[2], pr[3]);
    }
    if (idx < DIN*(NPROTO/2)){
        int d = idx >> 6, pp = idx & 63;
        g_PP[d][pp] = pk2(proto[(2*pp)*DHTOT + d], proto[(2*pp+1)*DHTOT + d]);
    }
    // pn2 parallel: block 0, thread (p = tid>>2, quarter = tid&3) sums 96 d each
    if (blockIdx.x == 0){
        int tid = threadIdx.x;
        int p = tid >> 2, r4 = tid & 3;
        float s = 0.f;
        const float* pr = proto + p*DHTOT + r4*96;
        #pragma unroll 8
        for (int d = 0; d < 96; ++d){ float v = pr[d]; s = fmaf(v, v, s); }
        s += __shfl_xor_sync(0xffffffffu, s, 1);
        s += __shfl_xor_sync(0xffffffffu, s, 2);
        if (r4 == 0) g_pn2[p] = s;
    }
}

// ============ DOTX precompute ============
extern __shared__ char psm[];
__global__ __launch_bounds__(512, 1)
void dotx_kernel(const float* __restrict__ x){
    u64* PPs = reinterpret_cast<u64*>(psm);        // [128 d][64 pp]
    const int tid = threadIdx.x;
    const int lane = tid & 31, wrp = tid >> 5;
    #pragma unroll
    for (int i = 0; i < 16; ++i)
        PPs[tid + i*512] = ((const u64*)g_PP)[tid + i*512];
    __syncthreads();

    const int pg = lane & 7;
    const int rp = (wrp << 2) | (lane >> 3);
    const size_t r0 = (size_t)blockIdx.x*128 + rp*2;
    const float4* xr0 = reinterpret_cast<const float4*>(x + r0*DIN);
    const float4* xr1 = reinterpret_cast<const float4*>(x + (r0+1)*DIN);

    u64 accA[8], accB[8];
    #pragma unroll
    for (int i = 0; i < 8; ++i){ accA[i] = 0ull; accB[i] = 0ull; }
    float n0 = 0.f, n1 = 0.f;

    #pragma unroll 4
    for (int dq = 0; dq < 32; ++dq){
        float4 fa = __ldcg(&xr0[dq]);
        float4 fb = __ldcg(&xr1[dq]);
        const float a[4] = {fa.x, fa.y, fa.z, fa.w};
        const float b[4] = {fb.x, fb.y, fb.z, fb.w};
        #pragma unroll
        for (int l = 0; l < 4; ++l){
            int d = dq*4 + l;
            u64 va = pk2(a[l], a[l]);
            u64 vb = pk2(b[l], b[l]);
            n0 = fmaf(a[l], a[l], n0);
            n1 = fmaf(b[l], b[l], n1);
            const u64* row = PPs + d*64 + pg;
            #pragma unroll
            for (int i = 0; i < 8; ++i){
                u64 pv = row[i*8];
                accA[i] = ffma2(va, pv, accA[i]);
                accB[i] = ffma2(vb, pv, accB[i]);
            }
        }
    }
    u64 nA2 = pk2(-0.5f*n0, -0.5f*n0);
    u64 nB2 = pk2(-0.5f*n1, -0.5f*n1);
    u64* DX = reinterpret_cast<u64*>(g_DOTX);
    #pragma unroll
    for (int i = 0; i < 8; ++i){
        int pp = i*8 + pg;
        DX[r0*64 + pp]     = add2(accA[i], nA2);
        DX[(r0+1)*64 + pp] = add2(accB[i], nB2);
    }
}

// ============ recurrent kernel ============
extern __shared__ char sm[];

__global__ void __cluster_dims__(CSZ,1,1) __launch_bounds__(NTHR, 1)
qlstm_kernel(const float* __restrict__ bf, const float* __restrict__ bi,
             const float* __restrict__ bg, const float* __restrict__ bo,
             float* __restrict__ out){
    const int tid  = threadIdx.x;
    const int lane = tid & 31;
    const int wrp  = tid >> 5;
    const uint32_t rank = ctarank();
    const int bbase = (blockIdx.x >> 2) * NB;
    const uint32_t base = smem_u32(sm);

    float4* PROT = reinterpret_cast<float4*>(sm + PROT_OFF);   // [16 q][128 p]
    u64*    PGp  = reinterpret_cast<u64*>(sm + PG_OFF);
    u64*    KD   = reinterpret_cast<u64*>(sm + KD_OFF);        // [p][10]
    const ulonglong2* KDv2 = reinterpret_cast<const ulonglong2*>(sm + KD_OFF);
    u64*    DOT  = reinterpret_cast<u64*>(sm + DOT_OFF);
    u64*    PD   = reinterpret_cast<u64*>(sm + PD_OFF);        // [4 dc][4 pr][128 p]
    u64*    CN2  = reinterpret_cast<u64*>(sm + CN2_OFF);
    u64*    CMBu = reinterpret_cast<u64*>(sm + CMB_OFF);       // [4 pr][64 h]
    float*  CMBF = reinterpret_cast<float*>(sm + CMB_OFF);

    // roles
    const int pK  = tid & 127;          // dist p / k p
    const int dcD = tid >> 7;           // dist h-chunk (0..3), 16 h each
    const int prK = tid >> 7;           // k batch-pair
    const int hL  = tid & 63;           // gate/reduce h_local
    const int pcG = tid >> 6;           // gate p-chunk (0..7)
    const int bR  = tid >> 6;           // reduce batch (0..7)
    const int hglob = (int)rank*64 + hL;

    // ---------- preamble ----------
    #pragma unroll
    for (int i = 0; i < 4; ++i){
        int idx = tid + i*NTHR;
        int q = idx >> 7, p = idx & 127;
        PROT[q*128 + p] = g_protoPack[32 + (int)rank*16 + q][p];
    }
    u64 wFI[16], wGO[16];
    #pragma unroll
    for (int j = 0; j < 16; ++j){
        float4 w = g_Wpack[pcG*16 + j][hglob];
        wFI[j] = pk2(w.x, w.y);
        wGO[j] = pk2(w.z, w.w);
    }
    if (tid < 256) CMBu[tid] = 0ull;    // zero hv

    const u64 bFI = pk2(bf[hglob], bi[hglob]);
    const u64 bGO = pk2(bg[hglob], bo[hglob]);
    const float pn2v = g_pn2[pK];

    // local mbarrier + peer addrs
    const uint32_t barLocal = base + MBAR_OFF;
    if (tid == 0) mbar_init(barLocal, CSZ - 1);   // 3 peer arrivals per phase
    uint32_t barPeer[CSZ - 1];
    {
        int n = 0;
        #pragma unroll
        for (uint32_t r = 0; r < CSZ; ++r)
            if (r != rank) barPeer[n++] = mapa_u32(barLocal, r);
    }

    // DSMEM addresses
    uint32_t dotAddr[CSZ], cnAddr[CSZ];
    {
        uint32_t dOff = base + DOT_OFF + (uint32_t)((((rank*4) + prK)*128 + pK)*8);
        uint32_t cOff = base + CN2_OFF + (uint32_t)((rank*4 + wrp)*8);   // cn2 role (tid<128)
        #pragma unroll
        for (uint32_t r = 0; r < CSZ; ++r){
            dotAddr[r] = mapa_u32(dOff, r);
            cnAddr[r]  = mapa_u32(cOff, r);
        }
    }

    const float* __restrict__ dxbase = g_DOTX + (size_t)(bbase + 2*prK)*NPROTO + pK;

    float cx = 0.f, hv = 0.f;
    uint32_t par = 0;

    __syncthreads();
    cl_arrive(); cl_wait();             // init (incl. mbarrier) visible cluster-wide

    for (int t = 0; t < TSTEPS; ++t){
        const uint32_t bufDot = (uint32_t)(t & 1) * 16384u;
        const uint32_t bufCn  = (uint32_t)(t & 1) * 128u;
        const int      bufU   = (t & 1) * 2048;
        const int      bufC   = (t & 1) * 16;

        // prefetch DOTX for this step (consumed in K after the handshake)
        const float* dxp = dxbase + (size_t)t*BSZ*NPROTO;
        float dxa = __ldcg(dxp);
        float dxb = __ldcg(dxp + NPROTO);

        __syncthreads();                // S1: hv(t-1) visible locally

        // ---- dist over h-quarter: thread=(pK, dcD), 16 h, all 4 pairs ----
        {
            u64 acc0 = 0ull, acc1 = 0ull, acc2 = 0ull, acc3 = 0ull;
            const float4* pp = PROT + (dcD*4)*128 + pK;
            const ulonglong2* cb = reinterpret_cast<const ulonglong2*>(CMBu + dcD*16);
            #pragma unroll
            for (int i = 0; i < 4; ++i){
                float4 pv = pp[i*128];
                u64 v0 = pk2(pv.x, pv.x), v1 = pk2(pv.y, pv.y);
                u64 v2 = pk2(pv.z, pv.z), v3 = pk2(pv.w, pv.w);
                #pragma unroll
                for (int pr = 0; pr < 4; ++pr){
                    ulonglong2 cA = cb[pr*32 + i*2    ];
                    ulonglong2 cB = cb[pr*32 + i*2 + 1];
                    u64 acc = (pr==0)?acc0:(pr==1)?acc1:(pr==2)?acc2:acc3;
                    acc = ffma2(cA.x, v0, acc);
                    acc = ffma2(cA.y, v1, acc);
                    acc = ffma2(cB.x, v2, acc);
                    acc = ffma2(cB.y, v3, acc);
                    if (pr==0) acc0=acc; else if (pr==1) acc1=acc; else if (pr==2) acc2=acc; else acc3=acc;
                }
            }
            PD[(dcD*4 + 0)*128 + pK] = acc0;
            PD[(dcD*4 + 1)*128 + pK] = acc1;
            PD[(dcD*4 + 2)*128 + pK] = acc2;
            PD[(dcD*4 + 3)*128 + pK] = acc3;
        }

        // ---- cn2_h partial (warps 0-3, pr = wrp) ----
        if (tid < 128){
            const u64* cb = CMBu + wrp*64;
            u64 c0 = cb[lane], c1 = cb[lane + 32];
            u64 a = ffma2(c0, c0, ffma2(c1, c1, 0ull));
            #pragma unroll
            for (int off = 16; off; off >>= 1)
                a = add2(a, shfl_xor64(a, off));
            if (lane == 0){
                #pragma unroll
                for (int r = 0; r < CSZ; ++r) st_cl64(cnAddr[r] + bufCn, a);
            }
        }
        __syncthreads();                // S2: PD complete

        // ---- sum dc partials + broadcast: thread=(pK, prK) ----
        {
            u64 s =        PD[(0*4 + prK)*128 + pK];
            s = add2(s,    PD[(1*4 + prK)*128 + pK]);
            s = add2(s,    PD[(2*4 + prK)*128 + pK]);
            s = add2(s,    PD[(3*4 + prK)*128 + pK]);
            #pragma unroll
            for (int r = 0; r < CSZ; ++r) st_cl64(dotAddr[r] + bufDot, s);
        }

        // ---- cluster handshake: mbarrier instead of barrier.cluster ----
        __syncthreads();                // SB: all DSMEM stores issued CTA-wide
        if (tid == 0){
            mbar_arrive_cluster(barPeer[0]);
            mbar_arrive_cluster(barPeer[1]);
            mbar_arrive_cluster(barPeer[2]);
        }
        mbar_wait_par(barLocal, par);
        par ^= 1u;

        // ---- k: reduce ranks + DOTX + exp ----
        {
            const u64* db = DOT + bufU;
            u64 ds =        db[(0*4 + prK)*128 + pK];
            ds = add2(ds,   db[(1*4 + prK)*128 + pK]);
            ds = add2(ds,   db[(2*4 + prK)*128 + pK]);
            ds = add2(ds,   db[(3*4 + prK)*128 + pK]);
            const u64* cn = CN2 + bufC;
            u64 cs = add2(add2(cn[0*4 + prK], cn[1*4 + prK]),
                          add2(cn[2*4 + prK], cn[3*4 + prK]));
            float d0, d1, c0, c1;
            upk2(ds, d0, d1); upk2(cs, c0, c1);
            float k0 = __expf(2.f*(d0 + dxa) - pn2v - c0);
            float k1 = __expf(2.f*(d1 + dxb) - pn2v - c1);
            ulonglong2 kk; kk.x = pk2(k0, k0); kk.y = pk2(k1, k1);
            *reinterpret_cast<ulonglong2*>(KD + pK*10 + 2*prK) = kk;
        }
        __syncthreads();                // S3: KD ready

        // ---- gate GEMM: thread=(hL, pcG), 16 p, 8 batches ----
        {
            u64 F0=0,F1=0,F2=0,F3=0,F4=0,F5=0,F6=0,F7=0;
            u64 G0=0,G1=0,G2=0,G3=0,G4=0,G5=0,G6=0,G7=0;
            const ulonglong2* kp = KDv2 + (pcG*16)*5;   // KD row = 10 u64 = 5 u128
            #pragma unroll 4
            for (int j = 0; j < 16; ++j){
                ulonglong2 kA = kp[j*5 + 0];
                ulonglong2 kB = kp[j*5 + 1];
                ulonglong2 kC = kp[j*5 + 2];
                ulonglong2 kE = kp[j*5 + 3];
                F0 = ffma2(wFI[j], kA.x, F0);  G0 = ffma2(wGO[j], kA.x, G0);
                F1 = ffma2(wFI[j], kA.y, F1);  G1 = ffma2(wGO[j], kA.y, G1);
                F2 = ffma2(wFI[j], kB.x, F2);  G2 = ffma2(wGO[j], kB.x, G2);
                F3 = ffma2(wFI[j], kB.y, F3);  G3 = ffma2(wGO[j], kB.y, G3);
                F4 = ffma2(wFI[j], kC.x, F4);  G4 = ffma2(wGO[j], kC.x, G4);
                F5 = ffma2(wFI[j], kC.y, F5);  G5 = ffma2(wGO[j], kC.y, G5);
                F6 = ffma2(wFI[j], kE.x, F6);  G6 = ffma2(wGO[j], kE.x, G6);
                F7 = ffma2(wFI[j], kE.y, F7);  G7 = ffma2(wGO[j], kE.y, G7);
            }
            u64* pg = PGp + (pcG*8)*2*64 + hL;
            pg[(0*2+0)*64] = F0; pg[(0*2+1)*64] = G0;
            pg[(1*2+0)*64] = F1; pg[(1*2+1)*64] = G1;
            pg[(2*2+0)*64] = F2; pg[(2*2+1)*64] = G2;
            pg[(3*2+0)*64] = F3; pg[(3*2+1)*64] = G3;
            pg[(4*2+0)*64] = F4; pg[(4*2+1)*64] = G4;
            pg[(5*2+0)*64] = F5; pg[(5*2+1)*64] = G5;
            pg[(6*2+0)*64] = F6; pg[(6*2+1)*64] = G6;
            pg[(7*2+0)*64] = F7; pg[(7*2+1)*64] = G7;
        }
        __syncthreads();                // S4: PG ready

        // ---- reduce + activations: thread=(hL, bR) ----
        {
            u64 Fa = bFI, Ga = bGO;
            #pragma unroll
            for (int c = 0; c < 8; ++c){
                Fa = add2(Fa, PGp[((c*8 + bR)*2 + 0)*64 + hL]);
                Ga = add2(Ga, PGp[((c*8 + bR)*2 + 1)*64 + hL]);
            }
            float fp, ip, gp, op;
            upk2(Fa, fp, ip); upk2(Ga, gp, op);
            float fv = sigmf(fp), iv = sigmf(ip), gv = tanhf_(gp), ov = sigmf(op);
            cx = fv*cx + iv*gv;
            hv = ov * tanhf_(cx);
            CMBF[((bR >> 1)*64 + hL)*2 + (bR & 1)] = hv;
            out[((size_t)t*BSZ + bbase + bR)*HID + hglob] = hv;
        }
        // loop-top S1 orders hv before next dist; DOT/CN2 double-buffer +
        // one handshake per step handles cross-CTA WAR (a peer's t+2 stores
        // require my t+1 arrive, issued after my t reads).
    }

    // ---- finals ----
    {
        const size_t TBH = (size_t)TSTEPS * BSZ * HID;
        const size_t BH  = (size_t)BSZ * HID;
        out[TBH + (size_t)(bbase + bR)*HID + hglob] = hv;
        out[TBH + BH + (size_t)(bbase + bR)*HID + hglob] = cx;
    }
}

extern "C" void kernel_launch(void* const* d_in, const int* in_sizes, int n_in,
                              void* d_out, int out_size){
    (void)in_sizes; (void)n_in; (void)out_size;
    const float* inputs = (const float*)d_in[0];
    const float* proto  = (const float*)d_in[1];
    const float* Wf     = (const float*)d_in[2];
    const float* bf     = (const float*)d_in[3];
    const float* Wi     = (const float*)d_in[4];
    const float* bi     = (const float*)d_in[5];
    const float* Wg     = (const float*)d_in[6];
    const float* bg     = (const float*)d_in[7];
    const float* Wo     = (const float*)d_in[8];
    const float* bo     = (const float*)d_in[9];
    float* out = (float*)d_out;

    cudaFuncSetAttribute(qlstm_kernel,
                         cudaFuncAttributeMaxDynamicSharedMemorySize, SMEM_TOTAL);
    cudaFuncSetAttribute(dotx_kernel,
                         cudaFuncAttributeMaxDynamicSharedMemorySize, 65536);

    pack_kernel<<<(HID*NPROTO + 511)/512, 512>>>(proto, Wf, Wi, Wg, Wo);
    dotx_kernel<<<(TSTEPS*BSZ)/128, 512, 65536>>>(inputs);
    qlstm_kernel<<<NCTA, NTHR, SMEM_TOTAL>>>(bf, bi, bg, bo, out);
}

// round 11
// speedup vs baseline: 1.6359x; 1.1369x over previous
#include <cuda_runtime.h>
#include <cstdint>

#define TSTEPS 512
#define BSZ    256
#define DIN    128
#define HID    256
#define NPROTO 128
#define DHTOT  384
#define NB     8            // batches per cluster
#define CSZ    4            // CTAs per cluster
#define NTHR   512
#define NCTA   128
#define DOTX_BLOCKS 1024    // (T*B)/128

__device__ float4 g_Wpack[NPROTO][HID];          // [p][h] = {wf, wi, wg, wo}
__device__ float4 g_protoPack[DHTOT/4][NPROTO];  // [q][p] = proto[p][4q..4q+3]
__device__ float  g_pn2[NPROTO];
__device__ float  g_DOTX[(size_t)TSTEPS*BSZ*NPROTO]; // dot(x,proto_x) - 0.5*||x||^2

typedef unsigned long long u64;

// ---------------- qlstm smem layout (bytes) ----------------
// PROT: 32768 @0 | PG: 65536 @32768 | KD: 10240 @98304
// DOT : [2 buf][4 r][4 pr][128 p] u64 32768 @108544
// PD  : [4 dc][4 pr][128 p] u64 16384 @141312
// CN2 : [4 pr] u64 (local, single buf) @157696 (pad 128)
// CMB : [4 pr][64 h] u64 2048 @157824
#define PROT_OFF 0
#define PG_OFF   32768
#define KD_OFF   98304
#define DOT_OFF  108544
#define PD_OFF   141312
#define CN2_OFF  157696
#define CMB_OFF  157824
#define SMEM_TOTAL 159872

__device__ __forceinline__ u64 pk2(float lo, float hi){
    u64 r; asm("mov.b64 %0, {%1,%2};" : "=l"(r) : "f"(lo), "f"(hi)); return r;
}
__device__ __forceinline__ void upk2(u64 v, float& lo, float& hi){
    asm("mov.b64 {%0,%1}, %2;" : "=f"(lo), "=f"(hi) : "l"(v));
}
__device__ __forceinline__ u64 ffma2(u64 a, u64 b, u64 c){
    u64 d; asm("fma.rn.f32x2 %0, %1, %2, %3;" : "=l"(d) : "l"(a), "l"(b), "l"(c)); return d;
}
__device__ __forceinline__ u64 add2(u64 a, u64 b){
    u64 d; asm("add.rn.f32x2 %0, %1, %2;" : "=l"(d) : "l"(a), "l"(b)); return d;
}
__device__ __forceinline__ float sigmf(float x){
    return __fdividef(1.f, 1.f + __expf(-x));
}
__device__ __forceinline__ float tanhf_(float x){
    return 1.f - __fdividef(2.f, __expf(2.f*x) + 1.f);
}
__device__ __forceinline__ uint32_t smem_u32(const void* p){
    uint32_t a;
    asm("{ .reg .u64 t; cvta.to.shared.u64 t, %1; cvt.u32.u64 %0, t; }" : "=r"(a) : "l"(p));
    return a;
}
__device__ __forceinline__ uint32_t ctarank(){
    uint32_t r; asm("mov.u32 %0, %%cluster_ctarank;" : "=r"(r)); return r;
}
__device__ __forceinline__ uint32_t mapa_u32(uint32_t local, uint32_t rank){
    uint32_t r; asm("mapa.shared::cluster.u32 %0, %1, %2;" : "=r"(r) : "r"(local), "r"(rank));
    return r;
}
__device__ __forceinline__ void st_cl64(uint32_t addr, u64 v){
    asm volatile("st.shared::cluster.b64 [%0], %1;" :: "r"(addr), "l"(v) : "memory");
}
__device__ __forceinline__ void cl_arrive(){
    asm volatile("barrier.cluster.arrive.aligned;" ::: "memory");
}
__device__ __forceinline__ void cl_wait(){
    asm volatile("barrier.cluster.wait.aligned;"   ::: "memory");
}
__device__ __forceinline__ void named_bar(int id){
    asm volatile("bar.sync %0, 64;" :: "r"(id) : "memory");
}
__device__ __forceinline__ u64 shfl_xor64(u64 v, int off){
    uint32_t lo = (uint32_t)v, hi = (uint32_t)(v >> 32);
    lo = __shfl_xor_sync(0xffffffffu, lo, off);
    hi = __shfl_xor_sync(0xffffffffu, hi, off);
    return ((u64)hi << 32) | lo;
}

// ============ unified preamble: dotx blocks (0..1023) + pack blocks (1024..1087) ============
extern __shared__ char psm[];
__global__ __launch_bounds__(512, 1)
void pre_kernel(const float* __restrict__ x,
                const float* __restrict__ proto,
                const float* __restrict__ Wf, const float* __restrict__ Wi,
                const float* __restrict__ Wg, const float* __restrict__ Wo){
    const int tid = threadIdx.x;
    if (blockIdx.x >= DOTX_BLOCKS){
        // ---- pack role ----
        int bb = blockIdx.x - DOTX_BLOCKS;          // 0..63
        int idx = bb*512 + tid;                     // 0..32767
        {
            int h = idx >> 7, pp = idx & (NPROTO-1);
            g_Wpack[pp][h] = make_float4(Wf[idx], Wi[idx], Wg[idx], Wo[idx]);
        }
        if (idx < (DHTOT/4)*NPROTO){
            int q = idx >> 7, pp = idx & (NPROTO-1);
            const float* pr = proto + pp*DHTOT + 4*q;
            g_protoPack[q][pp] = make_float4(pr[0], pr[1], pr[2], pr[3]);
        }
        if (bb == 0){
            int p = tid >> 2, r4 = tid & 3;
            float s = 0.f;
            const float* pr = proto + p*DHTOT + r4*96;
            #pragma unroll 8
            for (int d = 0; d < 96; ++d){ float v = pr[d]; s = fmaf(v, v, s); }
            s += __shfl_xor_sync(0xffffffffu, s, 1);
            s += __shfl_xor_sync(0xffffffffu, s, 2);
            if (r4 == 0) g_pn2[p] = s;
        }
        return;
    }

    // ---- dotx role: self-stage PP[d][pp] from proto (L2-resident after wave 1) ----
    u64* PPs = reinterpret_cast<u64*>(psm);         // [128 d][64 pp]
    const int lane = tid & 31, wrp = tid >> 5;
    #pragma unroll
    for (int i = 0; i < 16; ++i){
        int idx = tid + i*512;                      // 0..8191
        int d = idx >> 6, pp = idx & 63;
        PPs[idx] = pk2(proto[(2*pp)*DHTOT + d], proto[(2*pp+1)*DHTOT + d]);
    }
    __syncthreads();

    const int pg = lane & 7;
    const int rp = (wrp << 2) | (lane >> 3);
    const size_t r0 = (size_t)blockIdx.x*128 + rp*2;
    const float4* xr0 = reinterpret_cast<const float4*>(x + r0*DIN);
    const float4* xr1 = reinterpret_cast<const float4*>(x + (r0+1)*DIN);

    u64 accA[8], accB[8];
    #pragma unroll
    for (int i = 0; i < 8; ++i){ accA[i] = 0ull; accB[i] = 0ull; }
    float n0 = 0.f, n1 = 0.f;

    #pragma unroll 4
    for (int dq = 0; dq < 32; ++dq){
        float4 fa = __ldcg(&xr0[dq]);
        float4 fb = __ldcg(&xr1[dq]);
        const float a[4] = {fa.x, fa.y, fa.z, fa.w};
        const float b[4] = {fb.x, fb.y, fb.z, fb.w};
        #pragma unroll
        for (int l = 0; l < 4; ++l){
            int d = dq*4 + l;
            u64 va = pk2(a[l], a[l]);
            u64 vb = pk2(b[l], b[l]);
            n0 = fmaf(a[l], a[l], n0);
            n1 = fmaf(b[l], b[l], n1);
            const u64* row = PPs + d*64 + pg;
            #pragma unroll
            for (int i = 0; i < 8; ++i){
                u64 pv = row[i*8];
                accA[i] = ffma2(va, pv, accA[i]);
                accB[i] = ffma2(vb, pv, accB[i]);
            }
        }
    }
    u64 nA2 = pk2(-0.5f*n0, -0.5f*n0);
    u64 nB2 = pk2(-0.5f*n1, -0.5f*n1);
    u64* DX = reinterpret_cast<u64*>(g_DOTX);
    #pragma unroll
    for (int i = 0; i < 8; ++i){
        int pp = i*8 + pg;
        DX[r0*64 + pp]     = add2(accA[i], nA2);
        DX[(r0+1)*64 + pp] = add2(accB[i], nB2);
    }
}

// ============ recurrent kernel ============
extern __shared__ char sm[];

__global__ void __cluster_dims__(CSZ,1,1) __launch_bounds__(NTHR, 1)
qlstm_kernel(const float* __restrict__ bf, const float* __restrict__ bi,
             const float* __restrict__ bg, const float* __restrict__ bo,
             float* __restrict__ out){
    const int tid  = threadIdx.x;
    const int lane = tid & 31;
    const int wrp  = tid >> 5;
    const uint32_t rank = ctarank();
    const int bbase = (blockIdx.x >> 2) * NB;
    const uint32_t base = smem_u32(sm);

    float4* PROT = reinterpret_cast<float4*>(sm + PROT_OFF);   // [16 q][128 p]
    u64*    PGp  = reinterpret_cast<u64*>(sm + PG_OFF);
    u64*    KD   = reinterpret_cast<u64*>(sm + KD_OFF);        // [p][10]
    const ulonglong2* KDv2 = reinterpret_cast<const ulonglong2*>(sm + KD_OFF);
    u64*    DOT  = reinterpret_cast<u64*>(sm + DOT_OFF);
    u64*    PD   = reinterpret_cast<u64*>(sm + PD_OFF);        // [4 dc][4 pr][128 p]
    u64*    CN2  = reinterpret_cast<u64*>(sm + CN2_OFF);       // [4 pr] local
    u64*    CMBu = reinterpret_cast<u64*>(sm + CMB_OFF);       // [4 pr][64 h]
    float*  CMBF = reinterpret_cast<float*>(sm + CMB_OFF);

    // roles
    const int pK  = tid & 127;          // dist p / PD-sum p
    const int dcD = tid >> 7;           // dist h-chunk (0..3), 16 h each
    const int prK = tid >> 7;           // PD-sum batch-pair
    const int hL  = tid & 63;           // gate/reduce h_local
    const int pcG = tid >> 6;           // gate p-chunk (0..7) == warp-pair id
    const int bR  = tid >> 6;           // reduce batch (0..7)
    const int hglob = (int)rank*64 + hL;
    // k-phase pair-local mapping: same warp-pair that consumes KD in gate
    const int pK2  = (pcG << 4) + (tid & 15);   // p (0..127)
    const int prK2 = (tid >> 4) & 3;            // pair (0..3)

    // ---------- preamble ----------
    #pragma unroll
    for (int i = 0; i < 4; ++i){
        int idx = tid + i*NTHR;
        int q = idx >> 7, p = idx & 127;
        PROT[q*128 + p] = g_protoPack[32 + (int)rank*16 + q][p];
    }
    u64 wFI[16], wGO[16];
    #pragma unroll
    for (int j = 0; j < 16; ++j){
        float4 w = g_Wpack[pcG*16 + j][hglob];
        wFI[j] = pk2(w.x, w.y);
        wGO[j] = pk2(w.z, w.w);
    }
    if (tid < 256) CMBu[tid] = 0ull;    // zero hv

    const u64 bFI = pk2(bf[hglob], bi[hglob]);
    const u64 bGO = pk2(bg[hglob], bo[hglob]);
    const float pn2v = g_pn2[pK2];
    const u64 M1 = pk2(-1.f, -1.f);

    // DSMEM addresses (DOT broadcast, OLD mapping)
    uint32_t dotAddr[CSZ];
    {
        uint32_t dOff = base + DOT_OFF + (uint32_t)((((rank*4) + prK)*128 + pK)*8);
        #pragma unroll
        for (uint32_t r = 0; r < CSZ; ++r)
            dotAddr[r] = mapa_u32(dOff, r);
    }

    const float* __restrict__ dxbase = g_DOTX + (size_t)(bbase + 2*prK2)*NPROTO + pK2;

    float cx = 0.f, hv = 0.f;

    __syncthreads();
    cl_arrive(); cl_wait();             // init visible cluster-wide

    for (int t = 0; t < TSTEPS; ++t){
        const uint32_t bufDot = (uint32_t)(t & 1) * 16384u;
        const int      bufU   = (t & 1) * 2048;

        // prefetch DOTX for this step (consumed in k after the barrier)
        const float* dxp = dxbase + (size_t)t*BSZ*NPROTO;
        float dxa = __ldcg(dxp);
        float dxb = __ldcg(dxp + NPROTO);

        __syncthreads();                // S1: hv(t-1) visible locally

        // ---- dist over h-quarter: thread=(pK, dcD), 16 h, all 4 pairs ----
        {
            u64 acc0 = 0ull, acc1 = 0ull, acc2 = 0ull, acc3 = 0ull;
            const float4* pp = PROT + (dcD*4)*128 + pK;
            const ulonglong2* cb = reinterpret_cast<const ulonglong2*>(CMBu + dcD*16);
            #pragma unroll
            for (int i = 0; i < 4; ++i){
                float4 pv = pp[i*128];
                u64 v0 = pk2(pv.x, pv.x), v1 = pk2(pv.y, pv.y);
                u64 v2 = pk2(pv.z, pv.z), v3 = pk2(pv.w, pv.w);
                #pragma unroll
                for (int pr = 0; pr < 4; ++pr){
                    ulonglong2 cA = cb[pr*32 + i*2    ];
                    ulonglong2 cB = cb[pr*32 + i*2 + 1];
                    u64 acc = (pr==0)?acc0:(pr==1)?acc1:(pr==2)?acc2:acc3;
                    acc = ffma2(cA.x, v0, acc);
                    acc = ffma2(cA.y, v1, acc);
                    acc = ffma2(cB.x, v2, acc);
                    acc = ffma2(cB.y, v3, acc);
                    if (pr==0) acc0=acc; else if (pr==1) acc1=acc; else if (pr==2) acc2=acc; else acc3=acc;
                }
            }
            PD[(dcD*4 + 0)*128 + pK] = acc0;
            PD[(dcD*4 + 1)*128 + pK] = acc1;
            PD[(dcD*4 + 2)*128 + pK] = acc2;
            PD[(dcD*4 + 3)*128 + pK] = acc3;
        }

        // ---- cn2_h partial (warps 0-3, pr = wrp), LOCAL store only ----
        if (tid < 128){
            const u64* cb = CMBu + wrp*64;
            u64 c0 = cb[lane], c1 = cb[lane + 32];
            u64 a = ffma2(c0, c0, ffma2(c1, c1, 0ull));
            #pragma unroll
            for (int off = 16; off; off >>= 1)
                a = add2(a, shfl_xor64(a, off));
            if (lane == 0) CN2[wrp] = a;
        }
        __syncthreads();                // S2: PD + CN2 complete

        // ---- sum dc partials, fold cn2, broadcast s = 2*dot - cn2 ----
        {
            u64 s =        PD[(0*4 + prK)*128 + pK];
            s = add2(s,    PD[(1*4 + prK)*128 + pK]);
            s = add2(s,    PD[(2*4 + prK)*128 + pK]);
            s = add2(s,    PD[(3*4 + prK)*128 + pK]);
            s = ffma2(CN2[prK], M1, add2(s, s));
            #pragma unroll
            for (int r = 0; r < CSZ; ++r) st_cl64(dotAddr[r] + bufDot, s);
        }
        cl_arrive();
        cl_wait();                      // all ranks' partials visible

        // ---- k: pair-local mapping (pK2, prK2); producers == consumers ----
        {
            const u64* db = DOT + bufU;
            u64 ds =        db[(0*4 + prK2)*128 + pK2];
            ds = add2(ds,   db[(1*4 + prK2)*128 + pK2]);
            ds = add2(ds,   db[(2*4 + prK2)*128 + pK2]);
            ds = add2(ds,   db[(3*4 + prK2)*128 + pK2]);
            float d0, d1;
            upk2(ds, d0, d1);
            float k0 = __expf(fmaf(2.f, dxa, d0 - pn2v));
            float k1 = __expf(fmaf(2.f, dxb, d1 - pn2v));
            ulonglong2 kk; kk.x = pk2(k0, k0); kk.y = pk2(k1, k1);
            *reinterpret_cast<ulonglong2*>(KD + pK2*10 + 2*prK2) = kk;
        }
        named_bar(pcG + 1);             // pair-scoped: this pc's KD ready

        // ---- gate GEMM: thread=(hL, pcG), 16 p, 8 batches ----
        {
            u64 F0=0,F1=0,F2=0,F3=0,F4=0,F5=0,F6=0,F7=0;
            u64 G0=0,G1=0,G2=0,G3=0,G4=0,G5=0,G6=0,G7=0;
            const ulonglong2* kp = KDv2 + (pcG*16)*5;   // KD row = 10 u64 = 5 u128
            #pragma unroll 4
            for (int j = 0; j < 16; ++j){
                ulonglong2 kA = kp[j*5 + 0];
                ulonglong2 kB = kp[j*5 + 1];
                ulonglong2 kC = kp[j*5 + 2];
                ulonglong2 kE = kp[j*5 + 3];
                F0 = ffma2(wFI[j], kA.x, F0);  G0 = ffma2(wGO[j], kA.x, G0);
                F1 = ffma2(wFI[j], kA.y, F1);  G1 = ffma2(wGO[j], kA.y, G1);
                F2 = ffma2(wFI[j], kB.x, F2);  G2 = ffma2(wGO[j], kB.x, G2);
                F3 = ffma2(wFI[j], kB.y, F3);  G3 = ffma2(wGO[j], kB.y, G3);
                F4 = ffma2(wFI[j], kC.x, F4);  G4 = ffma2(wGO[j], kC.x, G4);
                F5 = ffma2(wFI[j], kC.y, F5);  G5 = ffma2(wGO[j], kC.y, G5);
                F6 = ffma2(wFI[j], kE.x, F6);  G6 = ffma2(wGO[j], kE.x, G6);
                F7 = ffma2(wFI[j], kE.y, F7);  G7 = ffma2(wGO[j], kE.y, G7);
            }
            u64* pg = PGp + (pcG*8)*2*64 + hL;
            pg[(0*2+0)*64] = F0; pg[(0*2+1)*64] = G0;
            pg[(1*2+0)*64] = F1; pg[(1*2+1)*64] = G1;
            pg[(2*2+0)*64] = F2; pg[(2*2+1)*64] = G2;
            pg[(3*2+0)*64] = F3; pg[(3*2+1)*64] = G3;
            pg[(4*2+0)*64] = F4; pg[(4*2+1)*64] = G4;
            pg[(5*2+0)*64] = F5; pg[(5*2+1)*64] = G5;
            pg[(6*2+0)*64] = F6; pg[(6*2+1)*64] = G6;
            pg[(7*2+0)*64] = F7; pg[(7*2+1)*64] = G7;
        }
        __syncthreads();                // S4: PG ready (all pc's)

        // ---- reduce + activations: thread=(hL, bR) ----
        {
            u64 Fa = bFI, Ga = bGO;
            #pragma unroll
            for (int c = 0; c < 8; ++c){
                Fa = add2(Fa, PGp[((c*8 + bR)*2 + 0)*64 + hL]);
                Ga = add2(Ga, PGp[((c*8 + bR)*2 + 1)*64 + hL]);
            }
            float fp, ip, gp, op;
            upk2(Fa, fp, ip); upk2(Ga, gp, op);
            float fv = sigmf(fp), iv = sigmf(ip), gv = tanhf_(gp), ov = sigmf(op);
            cx = fv*cx + iv*gv;
            hv = ov * tanhf_(cx);
            CMBF[((bR >> 1)*64 + hL)*2 + (bR & 1)] = hv;
            out[((size_t)t*BSZ + bbase + bR)*HID + hglob] = hv;
        }
        // loop-top S1 orders hv before next dist; DOT double-buffer +
        // one cluster barrier per step handles cross-CTA WAR.
    }

    // ---- finals ----
    {
        const size_t TBH = (size_t)TSTEPS * BSZ * HID;
        const size_t BH  = (size_t)BSZ * HID;
        out[TBH + (size_t)(bbase + bR)*HID + hglob] = hv;
        out[TBH + BH + (size_t)(bbase + bR)*HID + hglob] = cx;
    }
}

extern "C" void kernel_launch(void* const* d_in, const int* in_sizes, int n_in,
                              void* d_out, int out_size){
    (void)in_sizes; (void)n_in; (void)out_size;
    const float* inputs = (const float*)d_in[0];
    const float* proto  = (const float*)d_in[1];
    const float* Wf     = (const float*)d_in[2];
    const float* bf     = (const float*)d_in[3];
    const float* Wi     = (const float*)d_in[4];
    const float* bi     = (const float*)d_in[5];
    const float* Wg     = (const float*)d_in[6];
    const float* bg     = (const float*)d_in[7];
    const float* Wo     = (const float*)d_in[8];
    const float* bo     = (const float*)d_in[9];
    float* out = (float*)d_out;

    cudaFuncSetAttribute(qlstm_kernel,
                         cudaFuncAttributeMaxDynamicSharedMemorySize, SMEM_TOTAL);
    cudaFuncSetAttribute(pre_kernel,
                         cudaFuncAttributeMaxDynamicSharedMemorySize, 65536);

    pre_kernel<<<DOTX_BLOCKS + 64, 512, 65536>>>(inputs, proto, Wf, Wi, Wg, Wo);
    qlstm_kernel<<<NCTA, NTHR, SMEM_TOTAL>>>(bf, bi, bg, bo, out);
}

// round 16
// speedup vs baseline: 1.6881x; 1.0319x over previous
#include <cuda_runtime.h>
#include <cstdint>

#define TSTEPS 512
#define BSZ    256
#define DIN    128
#define HID    256
#define NPROTO 128
#define DHTOT  384
#define NB     8            // batches per cluster
#define CSZ    4            // CTAs per cluster
#define NTHR   512
#define NCTA   128
#define DOTX_BLOCKS 512     // (T*B)/256, 4 rows per thread

__device__ float4 g_Wpack[NPROTO][HID];          // [p][h] = {wf, wi, wg, wo}
__device__ float4 g_protoPack[DHTOT/4][NPROTO];  // [q][p] = proto[p][4q..4q+3]
__device__ float  g_pn2[NPROTO];
__device__ float  g_DOTX[(size_t)TSTEPS*BSZ*NPROTO]; // dot(x,proto_x) - 0.5*||x||^2

typedef unsigned long long u64;

// ---------------- qlstm smem layout (bytes) ----------------
// PROT: 32768 @0 | PG: [8 pc][8 b][64 h][{F,G}] u128 65536 @32768 | KD: 10240 @98304
// DOT : [2 buf][4 r][4 pr][128 p] u64 32768 @108544
// PD  : [4 dc][4 pr][128 p] u64 16384 @141312
// CN2 : [4 pr] u64 (local, single buf) @157696 (pad 128)
// CMB : [4 pr][64 h] u64 2048 @157824
#define PROT_OFF 0
#define PG_OFF   32768
#define KD_OFF   98304
#define DOT_OFF  108544
#define PD_OFF   141312
#define CN2_OFF  157696
#define CMB_OFF  157824
#define SMEM_TOTAL 159872

__device__ __forceinline__ u64 pk2(float lo, float hi){
    u64 r; asm("mov.b64 %0, {%1,%2};" : "=l"(r) : "f"(lo), "f"(hi)); return r;
}
__device__ __forceinline__ void upk2(u64 v, float& lo, float& hi){
    asm("mov.b64 {%0,%1}, %2;" : "=f"(lo), "=f"(hi) : "l"(v));
}
__device__ __forceinline__ u64 ffma2(u64 a, u64 b, u64 c){
    u64 d; asm("fma.rn.f32x2 %0, %1, %2, %3;" : "=l"(d) : "l"(a), "l"(b), "l"(c)); return d;
}
__device__ __forceinline__ u64 add2(u64 a, u64 b){
    u64 d; asm("add.rn.f32x2 %0, %1, %2;" : "=l"(d) : "l"(a), "l"(b)); return d;
}
__device__ __forceinline__ float sigmf(float x){
    return __fdividef(1.f, 1.f + __expf(-x));
}
__device__ __forceinline__ float tanhf_(float x){
    return 1.f - __fdividef(2.f, __expf(2.f*x) + 1.f);
}
__device__ __forceinline__ uint32_t smem_u32(const void* p){
    uint32_t a;
    asm("{ .reg .u64 t; cvta.to.shared.u64 t, %1; cvt.u32.u64 %0, t; }" : "=r"(a) : "l"(p));
    return a;
}
__device__ __forceinline__ uint32_t ctarank(){
    uint32_t r; asm("mov.u32 %0, %%cluster_ctarank;" : "=r"(r)); return r;
}
__device__ __forceinline__ uint32_t mapa_u32(uint32_t local, uint32_t rank){
    uint32_t r; asm("mapa.shared::cluster.u32 %0, %1, %2;" : "=r"(r) : "r"(local), "r"(rank));
    return r;
}
__device__ __forceinline__ void st_cl64(uint32_t addr, u64 v){
    asm volatile("st.shared::cluster.b64 [%0], %1;" :: "r"(addr), "l"(v) : "memory");
}
__device__ __forceinline__ void cl_arrive(){
    asm volatile("barrier.cluster.arrive.aligned;" ::: "memory");
}
__device__ __forceinline__ void cl_wait(){
    asm volatile("barrier.cluster.wait.aligned;"   ::: "memory");
}
__device__ __forceinline__ void named_bar(int id){
    asm volatile("bar.sync %0, 64;" :: "r"(id) : "memory");
}
__device__ __forceinline__ u64 shfl_xor64(u64 v, int off){
    uint32_t lo = (uint32_t)v, hi = (uint32_t)(v >> 32);
    lo = __shfl_xor_sync(0xffffffffu, lo, off);
    hi = __shfl_xor_sync(0xffffffffu, hi, off);
    return ((u64)hi << 32) | lo;
}

// ============ unified preamble: dotx blocks (0..511) + pack blocks (512..575) ============
extern __shared__ char psm[];
__global__ __launch_bounds__(512, 1)
void pre_kernel(const float* __restrict__ x,
                const float* __restrict__ proto,
                const float* __restrict__ Wf, const float* __restrict__ Wi,
                const float* __restrict__ Wg, const float* __restrict__ Wo){
    const int tid = threadIdx.x;
    if (blockIdx.x >= DOTX_BLOCKS){
        // ---- pack role ----
        int bb = blockIdx.x - DOTX_BLOCKS;          // 0..63
        int idx = bb*512 + tid;                     // 0..32767
        {
            int h = idx >> 7, pp = idx & (NPROTO-1);
            g_Wpack[pp][h] = make_float4(Wf[idx], Wi[idx], Wg[idx], Wo[idx]);
        }
        if (idx < (DHTOT/4)*NPROTO){
            int q = idx >> 7, pp = idx & (NPROTO-1);
            const float* pr = proto + pp*DHTOT + 4*q;
            g_protoPack[q][pp] = make_float4(pr[0], pr[1], pr[2], pr[3]);
        }
        if (bb == 0){
            int p = tid >> 2, r4 = tid & 3;
            float s = 0.f;
            const float* pr = proto + p*DHTOT + r4*96;
            #pragma unroll 8
            for (int d = 0; d < 96; ++d){ float v = pr[d]; s = fmaf(v, v, s); }
            s += __shfl_xor_sync(0xffffffffu, s, 1);
            s += __shfl_xor_sync(0xffffffffu, s, 2);
            if (r4 == 0) g_pn2[p] = s;
        }
        return;
    }

    // ---- dotx role: 4 rows per thread ----
    u64* PPs = reinterpret_cast<u64*>(psm);         // [128 d][64 pp]
    const int lane = tid & 31, wrp = tid >> 5;
    #pragma unroll
    for (int i = 0; i < 16; ++i){
        int idx = tid + i*512;                      // 0..8191
        int d = idx >> 6, pp = idx & 63;
        PPs[idx] = pk2(proto[(2*pp)*DHTOT + d], proto[(2*pp+1)*DHTOT + d]);
    }
    __syncthreads();

    const int pg = lane & 7;
    const int rq = (wrp << 2) | (lane >> 3);        // 0..63 row-quad
    const size_t r0 = (size_t)blockIdx.x*256 + rq*4;
    const float4* xr0 = reinterpret_cast<const float4*>(x + (r0+0)*DIN);
    const float4* xr1 = reinterpret_cast<const float4*>(x + (r0+1)*DIN);
    const float4* xr2 = reinterpret_cast<const float4*>(x + (r0+2)*DIN);
    const float4* xr3 = reinterpret_cast<const float4*>(x + (r0+3)*DIN);

    u64 acc[4][8];
    #pragma unroll
    for (int r = 0; r < 4; ++r)
        #pragma unroll
        for (int i = 0; i < 8; ++i) acc[r][i] = 0ull;
    float nn[4] = {0.f, 0.f, 0.f, 0.f};

    #pragma unroll 2
    for (int dq = 0; dq < 32; ++dq){
        float4 f0 = __ldcg(&xr0[dq]);
        float4 f1 = __ldcg(&xr1[dq]);
        float4 f2 = __ldcg(&xr2[dq]);
        float4 f3 = __ldcg(&xr3[dq]);
        const float a0[4] = {f0.x, f0.y, f0.z, f0.w};
        const float a1[4] = {f1.x, f1.y, f1.z, f1.w};
        const float a2[4] = {f2.x, f2.y, f2.z, f2.w};
        const float a3[4] = {f3.x, f3.y, f3.z, f3.w};
        #pragma unroll
        for (int l = 0; l < 4; ++l){
            int d = dq*4 + l;
            u64 v0 = pk2(a0[l], a0[l]);
            u64 v1 = pk2(a1[l], a1[l]);
            u64 v2 = pk2(a2[l], a2[l]);
            u64 v3 = pk2(a3[l], a3[l]);
            nn[0] = fmaf(a0[l], a0[l], nn[0]);
            nn[1] = fmaf(a1[l], a1[l], nn[1]);
            nn[2] = fmaf(a2[l], a2[l], nn[2]);
            nn[3] = fmaf(a3[l], a3[l], nn[3]);
            const u64* row = PPs + d*64 + pg;
            #pragma unroll
            for (int i = 0; i < 8; ++i){
                u64 pv = row[i*8];
                acc[0][i] = ffma2(v0, pv, acc[0][i]);
                acc[1][i] = ffma2(v1, pv, acc[1][i]);
                acc[2][i] = ffma2(v2, pv, acc[2][i]);
                acc[3][i] = ffma2(v3, pv, acc[3][i]);
            }
        }
    }
    u64* DX = reinterpret_cast<u64*>(g_DOTX);
    #pragma unroll
    for (int r = 0; r < 4; ++r){
        u64 nr = pk2(-0.5f*nn[r], -0.5f*nn[r]);
        #pragma unroll
        for (int i = 0; i < 8; ++i){
            int pp = i*8 + pg;
            DX[(r0 + r)*64 + pp] = add2(acc[r][i], nr);
        }
    }
}

// ============ recurrent kernel ============
extern __shared__ char sm[];

__global__ void __cluster_dims__(CSZ,1,1) __launch_bounds__(NTHR, 1)
qlstm_kernel(const float* __restrict__ bf, const float* __restrict__ bi,
             const float* __restrict__ bg, const float* __restrict__ bo,
             float* __restrict__ out){
    const int tid  = threadIdx.x;
    const int lane = tid & 31;
    const int wrp  = tid >> 5;
    const uint32_t rank = ctarank();
    const int bbase = (blockIdx.x >> 2) * NB;
    const uint32_t base = smem_u32(sm);

    float4* PROT = reinterpret_cast<float4*>(sm + PROT_OFF);   // [16 q][128 p]
    ulonglong2* PG2 = reinterpret_cast<ulonglong2*>(sm + PG_OFF); // [pc][b][64 h] {F,G}
    u64*    KD   = reinterpret_cast<u64*>(sm + KD_OFF);        // [p][10]
    const ulonglong2* KDv2 = reinterpret_cast<const ulonglong2*>(sm + KD_OFF);
    u64*    DOT  = reinterpret_cast<u64*>(sm + DOT_OFF);
    u64*    PD   = reinterpret_cast<u64*>(sm + PD_OFF);        // [4 dc][4 pr][128 p]
    u64*    CN2  = reinterpret_cast<u64*>(sm + CN2_OFF);       // [4 pr] local
    u64*    CMBu = reinterpret_cast<u64*>(sm + CMB_OFF);       // [4 pr][64 h]
    float*  CMBF = reinterpret_cast<float*>(sm + CMB_OFF);

    // roles
    const int pK  = tid & 127;          // dist p / PD-sum p
    const int dcD = tid >> 7;           // dist h-chunk (0..3), 16 h each
    const int prK = tid >> 7;           // PD-sum batch-pair
    const int hL  = tid & 63;           // gate/reduce h_local
    const int pcG = tid >> 6;           // gate p-chunk (0..7) == warp-pair id
    const int bR  = tid >> 6;           // reduce batch (0..7)
    const int hglob = (int)rank*64 + hL;
    // k-phase pair-local mapping: same warp-pair that consumes KD in gate
    const int pK2  = (pcG << 4) + (tid & 15);   // p (0..127)
    const int prK2 = (tid >> 4) & 3;            // pair (0..3)

    // ---------- preamble ----------
    #pragma unroll
    for (int i = 0; i < 4; ++i){
        int idx = tid + i*NTHR;
        int q = idx >> 7, p = idx & 127;
        PROT[q*128 + p] = g_protoPack[32 + (int)rank*16 + q][p];
    }
    u64 wFI[16], wGO[16];
    #pragma unroll
    for (int j = 0; j < 16; ++j){
        float4 w = g_Wpack[pcG*16 + j][hglob];
        wFI[j] = pk2(w.x, w.y);
        wGO[j] = pk2(w.z, w.w);
    }
    if (tid < 256) CMBu[tid] = 0ull;    // zero hv

    const u64 bFI = pk2(bf[hglob], bi[hglob]);
    const u64 bGO = pk2(bg[hglob], bo[hglob]);
    const float pn2v = g_pn2[pK2];
    const u64 M1 = pk2(-1.f, -1.f);

    // DSMEM addresses (DOT broadcast)
    uint32_t dotAddr[CSZ];
    {
        uint32_t dOff = base + DOT_OFF + (uint32_t)((((rank*4) + prK)*128 + pK)*8);
        #pragma unroll
        for (uint32_t r = 0; r < CSZ; ++r)
            dotAddr[r] = mapa_u32(dOff, r);
    }

    const float* __restrict__ dxbase = g_DOTX + (size_t)(bbase + 2*prK2)*NPROTO + pK2;

    float cx = 0.f, hv = 0.f;

    __syncthreads();
    cl_arrive(); cl_wait();             // init visible cluster-wide

    for (int t = 0; t < TSTEPS; ++t){
        const uint32_t bufDot = (uint32_t)(t & 1) * 16384u;
        const int      bufU   = (t & 1) * 2048;

        // prefetch DOTX for this step (consumed in k after the barrier)
        const float* dxp = dxbase + (size_t)t*BSZ*NPROTO;
        float dxa = __ldcg(dxp);
        float dxb = __ldcg(dxp + NPROTO);

        __syncthreads();                // S1: hv(t-1) visible locally

        // ---- dist over h-quarter: thread=(pK, dcD), 16 h, all 4 pairs ----
        {
            u64 acc0 = 0ull, acc1 = 0ull, acc2 = 0ull, acc3 = 0ull;
            const float4* pp = PROT + (dcD*4)*128 + pK;
            const ulonglong2* cb = reinterpret_cast<const ulonglong2*>(CMBu + dcD*16);
            #pragma unroll
            for (int i = 0; i < 4; ++i){
                float4 pv = pp[i*128];
                u64 v0 = pk2(pv.x, pv.x), v1 = pk2(pv.y, pv.y);
                u64 v2 = pk2(pv.z, pv.z), v3 = pk2(pv.w, pv.w);
                #pragma unroll
                for (int pr = 0; pr < 4; ++pr){
                    ulonglong2 cA = cb[pr*32 + i*2    ];
                    ulonglong2 cB = cb[pr*32 + i*2 + 1];
                    u64 acc = (pr==0)?acc0:(pr==1)?acc1:(pr==2)?acc2:acc3;
                    acc = ffma2(cA.x, v0, acc);
                    acc = ffma2(cA.y, v1, acc);
                    acc = ffma2(cB.x, v2, acc);
                    acc = ffma2(cB.y, v3, acc);
                    if (pr==0) acc0=acc; else if (pr==1) acc1=acc; else if (pr==2) acc2=acc; else acc3=acc;
                }
            }
            PD[(dcD*4 + 0)*128 + pK] = acc0;
            PD[(dcD*4 + 1)*128 + pK] = acc1;
            PD[(dcD*4 + 2)*128 + pK] = acc2;
            PD[(dcD*4 + 3)*128 + pK] = acc3;
        }

        // ---- cn2_h partial (warps 0-3, pr = wrp), LOCAL store only ----
        if (tid < 128){
            const u64* cb = CMBu + wrp*64;
            u64 c0 = cb[lane], c1 = cb[lane + 32];
            u64 a = ffma2(c0, c0, ffma2(c1, c1, 0ull));
            #pragma unroll
            for (int off = 16; off; off >>= 1)
                a = add2(a, shfl_xor64(a, off));
            if (lane == 0) CN2[wrp] = a;
        }
        __syncthreads();                // S2: PD + CN2 complete

        // ---- sum dc partials, fold cn2, broadcast s = 2*dot - cn2 ----
        {
            u64 s =        PD[(0*4 + prK)*128 + pK];
            s = add2(s,    PD[(1*4 + prK)*128 + pK]);
            s = add2(s,    PD[(2*4 + prK)*128 + pK]);
            s = add2(s,    PD[(3*4 + prK)*128 + pK]);
            s = ffma2(CN2[prK], M1, add2(s, s));
            #pragma unroll
            for (int r = 0; r < CSZ; ++r) st_cl64(dotAddr[r] + bufDot, s);
        }
        cl_arrive();
        cl_wait();                      // all ranks' partials visible

        // ---- k: pair-local mapping (pK2, prK2); producers == consumers ----
        {
            const u64* db = DOT + bufU;
            u64 ds =        db[(0*4 + prK2)*128 + pK2];
            ds = add2(ds,   db[(1*4 + prK2)*128 + pK2]);
            ds = add2(ds,   db[(2*4 + prK2)*128 + pK2]);
            ds = add2(ds,   db[(3*4 + prK2)*128 + pK2]);
            float d0, d1;
            upk2(ds, d0, d1);
            float k0 = __expf(fmaf(2.f, dxa, d0 - pn2v));
            float k1 = __expf(fmaf(2.f, dxb, d1 - pn2v));
            ulonglong2 kk; kk.x = pk2(k0, k0); kk.y = pk2(k1, k1);
            *reinterpret_cast<ulonglong2*>(KD + pK2*10 + 2*prK2) = kk;
        }
        named_bar(pcG + 1);             // pair-scoped: this pc's KD ready

        // ---- gate GEMM: thread=(hL, pcG), 16 p, 8 batches ----
        {
            u64 F0=0,F1=0,F2=0,F3=0,F4=0,F5=0,F6=0,F7=0;
            u64 G0=0,G1=0,G2=0,G3=0,G4=0,G5=0,G6=0,G7=0;
            const ulonglong2* kp = KDv2 + (pcG*16)*5;   // KD row = 10 u64 = 5 u128
            #pragma unroll 4
            for (int j = 0; j < 16; ++j){
                ulonglong2 kA = kp[j*5 + 0];
                ulonglong2 kB = kp[j*5 + 1];
                ulonglong2 kC = kp[j*5 + 2];
                ulonglong2 kE = kp[j*5 + 3];
                F0 = ffma2(wFI[j], kA.x, F0);  G0 = ffma2(wGO[j], kA.x, G0);
                F1 = ffma2(wFI[j], kA.y, F1);  G1 = ffma2(wGO[j], kA.y, G1);
                F2 = ffma2(wFI[j], kB.x, F2);  G2 = ffma2(wGO[j], kB.x, G2);
                F3 = ffma2(wFI[j], kB.y, F3);  G3 = ffma2(wGO[j], kB.y, G3);
                F4 = ffma2(wFI[j], kC.x, F4);  G4 = ffma2(wGO[j], kC.x, G4);
                F5 = ffma2(wFI[j], kC.y, F5);  G5 = ffma2(wGO[j], kC.y, G5);
                F6 = ffma2(wFI[j], kE.x, F6);  G6 = ffma2(wGO[j], kE.x, G6);
                F7 = ffma2(wFI[j], kE.y, F7);  G7 = ffma2(wGO[j], kE.y, G7);
            }
            // interleaved {F,G} stores: one STS.128 per batch
            ulonglong2* pg = PG2 + (pcG*8)*64 + hL;
            ulonglong2 v;
            v.x = F0; v.y = G0; pg[0*64] = v;
            v.x = F1; v.y = G1; pg[1*64] = v;
            v.x = F2; v.y = G2; pg[2*64] = v;
            v.x = F3; v.y = G3; pg[3*64] = v;
            v.x = F4; v.y = G4; pg[4*64] = v;
            v.x = F5; v.y = G5; pg[5*64] = v;
            v.x = F6; v.y = G6; pg[6*64] = v;
            v.x = F7; v.y = G7; pg[7*64] = v;
        }
        __syncthreads();                // S4: PG ready (all pc's)

        // ---- reduce + activations: thread=(hL, bR), LDS.128 per chunk ----
        {
            u64 Fa = bFI, Ga = bGO;
            const ulonglong2* pgr = PG2 + bR*64 + hL;
            #pragma unroll
            for (int c = 0; c < 8; ++c){
                ulonglong2 v = pgr[c*512];      // pc stride = 8*64 u128
                Fa = add2(Fa, v.x);
                Ga = add2(Ga, v.y);
            }
            float fp, ip, gp, op;
            upk2(Fa, fp, ip); upk2(Ga, gp, op);
            float fv = sigmf(fp), iv = sigmf(ip), gv = tanhf_(gp), ov = sigmf(op);
            cx = fv*cx + iv*gv;
            hv = ov * tanhf_(cx);
            CMBF[((bR >> 1)*64 + hL)*2 + (bR & 1)] = hv;
            out[((size_t)t*BSZ + bbase + bR)*HID + hglob] = hv;
        }
        // loop-top S1 orders hv before next dist; DOT double-buffer +
        // one cluster barrier per step handles cross-CTA WAR.
    }

    // ---- finals ----
    {
        const size_t TBH = (size_t)TSTEPS * BSZ * HID;
        const size_t BH  = (size_t)BSZ * HID;
        out[TBH + (size_t)(bbase + bR)*HID + hglob] = hv;
        out[TBH + BH + (size_t)(bbase + bR)*HID + hglob] = cx;
    }
}

extern "C" void kernel_launch(void* const* d_in, const int* in_sizes, int n_in,
                              void* d_out, int out_size){
    (void)in_sizes; (void)n_in; (void)out_size;
    const float* inputs = (const float*)d_in[0];
    const float* proto  = (const float*)d_in[1];
    const float* Wf     = (const float*)d_in[2];
    const float* bf     = (const float*)d_in[3];
    const float* Wi     = (const float*)d_in[4];
    const float* bi     = (const float*)d_in[5];
    const float* Wg     = (const float*)d_in[6];
    const float* bg     = (const float*)d_in[7];
    const float* Wo     = (const float*)d_in[8];
    const float* bo     = (const float*)d_in[9];
    float* out = (float*)d_out;

    cudaFuncSetAttribute(qlstm_kernel,
                         cudaFuncAttributeMaxDynamicSharedMemorySize, SMEM_TOTAL);
    cudaFuncSetAttribute(pre_kernel,
                         cudaFuncAttributeMaxDynamicSharedMemorySize, 65536);

    pre_kernel<<<DOTX_BLOCKS + 64, 512, 65536>>>(inputs, proto, Wf, Wi, Wg, Wo);
    qlstm_kernel<<<NCTA, NTHR, SMEM_TOTAL>>>(bf, bi, bg, bo, out);
}